// round 2
// baseline (speedup 1.0000x reference)
#include <cuda_runtime.h>
#include <math.h>

// Problem constants (Gemma4 FFN)
#define TT 2048     // tokens = B*S
#define HH 2048     // hidden
#define II 8192     // dense intermediate
#define MM 1024     // moe intermediate
#define NE 8        // experts
#define ECAP (NE * TT)
#define ROOTF 0.02209708691207961f  // H^-0.5

// ---------------- scratch (device globals; no allocation allowed) ----------------
__device__ float g_dense_in[TT * HH];
__device__ float g_moe_in[TT * HH];
__device__ float g_xr[TT * HH];
__device__ float g_dense_raw[TT * HH];
__device__ float g_bufG[TT * II];   // dense gate  / moe gate (capacity ECAP*MM == TT*II)
__device__ float g_bufU[TT * II];   // dense up    / moe up
__device__ float g_bufH[TT * II];   // dense glu   / moe glu
__device__ float g_eo[ECAP * HH];   // per-expert-row outputs
__device__ int   g_cursor[NE];
__device__ int   g_tok_of_row[ECAP];
__device__ int   g_row_of_token[TT * 2];
__device__ float g_topw[TT * 2];

// ---------------- helpers ----------------
__device__ __forceinline__ float blk_reduce(float v, volatile float* sh) {
    int lane = threadIdx.x & 31, w = threadIdx.x >> 5;
#pragma unroll
    for (int o = 16; o; o >>= 1) v += __shfl_xor_sync(0xffffffffu, v, o);
    if (lane == 0) sh[w] = v;
    __syncthreads();
    float r = (threadIdx.x < 8) ? sh[threadIdx.x] : 0.f;
    if (w == 0) {
#pragma unroll
        for (int o = 4; o; o >>= 1) r += __shfl_xor_sync(0xffffffffu, r, o);
        if (lane == 0) sh[8] = r;
    }
    __syncthreads();
    float out = sh[8];
    __syncthreads();
    return out;
}

__device__ __forceinline__ float gelu_tanh(float x) {
    float x3 = x * x * x;
    float t = tanhf(0.7978845608028654f * (x + 0.044715f * x3));
    return 0.5f * x * (1.f + t);
}

// ---------------- prep: one sumsq per token feeds all 3 pre-norms ----------------
__global__ void prep_kernel(const float* __restrict__ x,
                            const float* __restrict__ pre1,
                            const float* __restrict__ pre2,
                            const float* __restrict__ rscale)
{
    __shared__ float sh[9];
    int t = blockIdx.x, tid = threadIdx.x;
    if (t == 0 && tid < NE) g_cursor[tid] = 0;   // reset router cursors each launch
    const float* xrow = x + (long long)t * HH;
    float v[8]; float ss = 0.f;
#pragma unroll
    for (int i = 0; i < 8; i++) { v[i] = xrow[tid + i * 256]; ss += v[i] * v[i]; }
    ss = blk_reduce(ss, sh);
    float inv = rsqrtf(ss * (1.f / HH) + 1e-6f);
#pragma unroll
    for (int i = 0; i < 8; i++) {
        int h = tid + i * 256;
        float y = v[i] * inv;
        long long o = (long long)t * HH + h;
        g_dense_in[o] = y * pre1[h];
        g_moe_in[o]   = y * pre2[h];
        g_xr[o]       = y * rscale[h] * ROOTF;
    }
}

// ---------------- router: logits, softmax top-2, slot assignment ----------------
__global__ void router_kernel(const float* __restrict__ rw,
                              const float* __restrict__ pes)
{
    __shared__ float sred[8][NE];
    int t = blockIdx.x, tid = threadIdx.x;
    float acc[NE];
#pragma unroll
    for (int e = 0; e < NE; e++) acc[e] = 0.f;
    const float* xr = g_xr + (long long)t * HH;
#pragma unroll
    for (int i = 0; i < 8; i++) {
        int h = tid + i * 256;
        float xv = xr[h];
        float4 w0 = *(const float4*)(rw + (long long)h * NE);
        float4 w1 = *(const float4*)(rw + (long long)h * NE + 4);
        acc[0] += xv * w0.x; acc[1] += xv * w0.y; acc[2] += xv * w0.z; acc[3] += xv * w0.w;
        acc[4] += xv * w1.x; acc[5] += xv * w1.y; acc[6] += xv * w1.z; acc[7] += xv * w1.w;
    }
#pragma unroll
    for (int e = 0; e < NE; e++) {
#pragma unroll
        for (int o = 16; o; o >>= 1) acc[e] += __shfl_xor_sync(0xffffffffu, acc[e], o);
    }
    int w = tid >> 5, lane = tid & 31;
    if (lane == 0) {
#pragma unroll
        for (int e = 0; e < NE; e++) sred[w][e] = acc[e];
    }
    __syncthreads();
    if (tid == 0) {
        float l[NE];
#pragma unroll
        for (int e = 0; e < NE; e++) {
            float s = 0.f;
#pragma unroll
            for (int ww = 0; ww < 8; ww++) s += sred[ww][e];
            l[e] = s;
        }
        int i0 = 0;
#pragma unroll
        for (int e = 1; e < NE; e++) if (l[e] > l[i0]) i0 = e;
        int i1 = (i0 == 0) ? 1 : 0;
#pragma unroll
        for (int e = 0; e < NE; e++) if (e != i0 && l[e] > l[i1]) i1 = e;
        // top2 renormalized softmax weights: p0/(p0+p1) = 1/(1+exp(l1-l0))
        float d = expf(l[i1] - l[i0]);         // <= 1
        float w0v = 1.f / (1.f + d) * pes[i0];
        float w1v = d / (1.f + d) * pes[i1];
        // slot assignment: atomic order varies, but final output depends only on
        // per-token row contents -> bitwise deterministic result.
        int s0 = atomicAdd(&g_cursor[i0], 1);
        int r0 = i0 * TT + s0;
        g_tok_of_row[r0] = t; g_row_of_token[2 * t] = r0; g_topw[2 * t] = w0v;
        int s1 = atomicAdd(&g_cursor[i1], 1);
        int r1 = i1 * TT + s1;
        g_tok_of_row[r1] = t; g_row_of_token[2 * t + 1] = r1; g_topw[2 * t + 1] = w1v;
    }
}

// ---------------- SGEMM: 128x128x16 tile, 8x8/thread, prefetch pipeline ----------------
#define BM 128
#define BN 128
#define BK 16

__global__ __launch_bounds__(256, 2)
void sgemm_kernel(const float* __restrict__ A, int lda, long long aZ,
                  const float* __restrict__ B, int ldb, long long bZ,
                  float* __restrict__ C, int ldc, long long cZ,
                  int Kd,
                  const int* __restrict__ rowidx, int ridxZ,
                  const int* __restrict__ counts)
{
    const int e = blockIdx.z;
    A += (long long)e * aZ; B += (long long)e * bZ; C += (long long)e * cZ;
    int mlimit = 1 << 30;
    if (counts) {
        mlimit = counts[e];
        if ((int)(blockIdx.y * BM) >= mlimit) return;
    }

    __shared__ float As[BK][BM + 1];           // [k][m], pad -> stride 129 (conflict-lean)
    __shared__ __align__(16) float Bs[BK][BN]; // [k][n]

    const int tid = threadIdx.x;
    const int tx = tid & 15;
    const int ty = tid >> 4;
    const int m0 = blockIdx.y * BM;
    const int n0 = blockIdx.x * BN;

    // A load slots: 512 float4 slots (m, kq), 2 per thread (gather-capable)
    const float* aptr[2];
    int a_m[2], a_k[2];
#pragma unroll
    for (int i = 0; i < 2; i++) {
        int s = tid + 256 * i;
        int am = s >> 2, kq = s & 3;
        a_m[i] = am; a_k[i] = kq * 4;
        int row = m0 + am;
        int arow = row;
        if (rowidx) arow = (row < mlimit) ? rowidx[(long long)e * ridxZ + row] : 0;
        aptr[i] = A + (long long)arow * lda + kq * 4;
    }
    int b_k[2], b_n[2];
#pragma unroll
    for (int i = 0; i < 2; i++) {
        int s = tid + 256 * i;
        b_k[i] = s >> 5;
        b_n[i] = (s & 31) * 4;
    }

    float acc[8][8];
#pragma unroll
    for (int i = 0; i < 8; i++)
#pragma unroll
        for (int j = 0; j < 8; j++) acc[i][j] = 0.f;

    float4 ra[2], rb[2];
#pragma unroll
    for (int i = 0; i < 2; i++) ra[i] = *(const float4*)(aptr[i]);
#pragma unroll
    for (int i = 0; i < 2; i++) rb[i] = *(const float4*)(B + (long long)b_k[i] * ldb + n0 + b_n[i]);

    const int ktiles = Kd / BK;
    for (int kt = 0; kt < ktiles; kt++) {
#pragma unroll
        for (int i = 0; i < 2; i++) {
            As[a_k[i] + 0][a_m[i]] = ra[i].x;
            As[a_k[i] + 1][a_m[i]] = ra[i].y;
            As[a_k[i] + 2][a_m[i]] = ra[i].z;
            As[a_k[i] + 3][a_m[i]] = ra[i].w;
        }
#pragma unroll
        for (int i = 0; i < 2; i++)
            *(float4*)&Bs[b_k[i]][b_n[i]] = rb[i];
        __syncthreads();
        if (kt + 1 < ktiles) {                 // prefetch next tile into regs
            int ko = (kt + 1) * BK;
#pragma unroll
            for (int i = 0; i < 2; i++) ra[i] = *(const float4*)(aptr[i] + ko);
#pragma unroll
            for (int i = 0; i < 2; i++)
                rb[i] = *(const float4*)(B + (long long)(ko + b_k[i]) * ldb + n0 + b_n[i]);
        }
#pragma unroll
        for (int kk = 0; kk < BK; kk++) {
            float af[8], bf[8];
#pragma unroll
            for (int i = 0; i < 4; i++) {
                af[i]     = As[kk][ty * 4 + i];
                af[4 + i] = As[kk][64 + ty * 4 + i];
            }
            float4 b0 = *(const float4*)&Bs[kk][tx * 4];
            float4 b1 = *(const float4*)&Bs[kk][64 + tx * 4];
            bf[0] = b0.x; bf[1] = b0.y; bf[2] = b0.z; bf[3] = b0.w;
            bf[4] = b1.x; bf[5] = b1.y; bf[6] = b1.z; bf[7] = b1.w;
#pragma unroll
            for (int i = 0; i < 8; i++)
#pragma unroll
                for (int j = 0; j < 8; j++)
                    acc[i][j] = fmaf(af[i], bf[j], acc[i][j]);
        }
        __syncthreads();
    }

#pragma unroll
    for (int i = 0; i < 8; i++) {
        int rl = (i < 4) ? (ty * 4 + i) : (64 + ty * 4 + i - 4);
        int r = m0 + rl;
        if (r >= mlimit) continue;
        float* Crow = C + (long long)r * ldc + n0;
        *(float4*)(Crow + tx * 4)      = make_float4(acc[i][0], acc[i][1], acc[i][2], acc[i][3]);
        *(float4*)(Crow + 64 + tx * 4) = make_float4(acc[i][4], acc[i][5], acc[i][6], acc[i][7]);
    }
}

// ---------------- pointwise GLU ----------------
__global__ void glumul_kernel(const float* __restrict__ g,
                              const float* __restrict__ u,
                              float* __restrict__ h, long long n4)
{
    long long i = (long long)blockIdx.x * blockDim.x + threadIdx.x;
    if (i >= n4) return;
    float4 gv = *(const float4*)(g + i * 4);
    float4 uv = *(const float4*)(u + i * 4);
    float4 hv;
    hv.x = gelu_tanh(gv.x) * uv.x;
    hv.y = gelu_tanh(gv.y) * uv.y;
    hv.z = gelu_tanh(gv.z) * uv.z;
    hv.w = gelu_tanh(gv.w) * uv.w;
    *(float4*)(h + i * 4) = hv;
}

__global__ void glumul_moe_kernel()
{
    int row = blockIdx.x;
    int e = row >> 11, slot = row & (TT - 1);
    if (slot >= g_cursor[e]) return;        // skip unassigned capacity rows
    long long o = (long long)row * MM + threadIdx.x * 4;
    float4 gv = *(const float4*)(g_bufG + o);
    float4 uv = *(const float4*)(g_bufU + o);
    float4 hv;
    hv.x = gelu_tanh(gv.x) * uv.x;
    hv.y = gelu_tanh(gv.y) * uv.y;
    hv.z = gelu_tanh(gv.z) * uv.z;
    hv.w = gelu_tanh(gv.w) * uv.w;
    *(float4*)(g_bufH + o) = hv;
}

// ---------------- final: rms_post1(dense) + combine + rms_post2 + rms_post ----------------
__global__ void final_kernel(const float* __restrict__ post1,
                             const float* __restrict__ post2,
                             const float* __restrict__ post,
                             float* __restrict__ out)
{
    __shared__ float sh[9];
    int t = blockIdx.x, tid = threadIdx.x;
    int r0 = g_row_of_token[2 * t], r1 = g_row_of_token[2 * t + 1];
    float w0 = g_topw[2 * t], w1 = g_topw[2 * t + 1];
    float dv[8], mv[8];
    float ssd = 0.f, ssm = 0.f;
#pragma unroll
    for (int i = 0; i < 8; i++) {
        int h = tid + i * 256;
        float d = g_dense_raw[(long long)t * HH + h];
        float m = w0 * g_eo[(long long)r0 * HH + h] + w1 * g_eo[(long long)r1 * HH + h];
        dv[i] = d; mv[i] = m;
        ssd += d * d; ssm += m * m;
    }
    ssd = blk_reduce(ssd, sh);
    ssm = blk_reduce(ssm, sh);
    float invd = rsqrtf(ssd * (1.f / HH) + 1e-6f);
    float invm = rsqrtf(ssm * (1.f / HH) + 1e-6f);
    float yv[8]; float ssy = 0.f;
#pragma unroll
    for (int i = 0; i < 8; i++) {
        int h = tid + i * 256;
        float y = dv[i] * invd * post1[h] + mv[i] * invm * post2[h];
        yv[i] = y; ssy += y * y;
    }
    ssy = blk_reduce(ssy, sh);
    float invy = rsqrtf(ssy * (1.f / HH) + 1e-6f);
#pragma unroll
    for (int i = 0; i < 8; i++) {
        int h = tid + i * 256;
        out[(long long)t * HH + h] = yv[i] * invy * post[h];
    }
}

// ---------------- launch ----------------
extern "C" void kernel_launch(void* const* d_in, const int* in_sizes, int n_in,
                              void* d_out, int out_size)
{
    (void)in_sizes; (void)n_in; (void)out_size;
    const float* x            = (const float*)d_in[0];
    const float* rn_pre1      = (const float*)d_in[1];
    const float* rn_pre2      = (const float*)d_in[2];
    const float* rn_post1     = (const float*)d_in[3];
    const float* rn_post2     = (const float*)d_in[4];
    const float* rn_post      = (const float*)d_in[5];
    const float* w_gate       = (const float*)d_in[6];
    const float* w_up         = (const float*)d_in[7];
    const float* w_down       = (const float*)d_in[8];
    const float* router_w     = (const float*)d_in[9];
    const float* router_scale = (const float*)d_in[10];
    const float* pes          = (const float*)d_in[11];
    const float* we_gate      = (const float*)d_in[12];
    const float* we_up        = (const float*)d_in[13];
    const float* we_down      = (const float*)d_in[14];
    float* out = (float*)d_out;

    float *p_dense_in, *p_moe_in, *p_dense_raw, *p_bufG, *p_bufU, *p_bufH, *p_eo;
    int *p_tok, *p_cur;
    cudaGetSymbolAddress((void**)&p_dense_in,  g_dense_in);
    cudaGetSymbolAddress((void**)&p_moe_in,    g_moe_in);
    cudaGetSymbolAddress((void**)&p_dense_raw, g_dense_raw);
    cudaGetSymbolAddress((void**)&p_bufG,      g_bufG);
    cudaGetSymbolAddress((void**)&p_bufU,      g_bufU);
    cudaGetSymbolAddress((void**)&p_bufH,      g_bufH);
    cudaGetSymbolAddress((void**)&p_eo,        g_eo);
    cudaGetSymbolAddress((void**)&p_tok,       g_tok_of_row);
    cudaGetSymbolAddress((void**)&p_cur,       g_cursor);

    prep_kernel<<<TT, 256>>>(x, rn_pre1, rn_pre2, router_scale);
    router_kernel<<<TT, 256>>>(router_w, pes);

    // dense branch
    dim3 gGU(II / BN, TT / BM, 1);
    sgemm_kernel<<<gGU, 256>>>(p_dense_in, HH, 0, w_gate, II, 0, p_bufG, II, 0, HH, nullptr, 0, nullptr);
    sgemm_kernel<<<gGU, 256>>>(p_dense_in, HH, 0, w_up,   II, 0, p_bufU, II, 0, HH, nullptr, 0, nullptr);
    long long nd4 = (long long)TT * II / 4;
    glumul_kernel<<<(unsigned)((nd4 + 255) / 256), 256>>>(p_bufG, p_bufU, p_bufH, nd4);
    dim3 gDn(HH / BN, TT / BM, 1);
    sgemm_kernel<<<gDn, 256>>>(p_bufH, II, 0, w_down, HH, 0, p_dense_raw, HH, 0, II, nullptr, 0, nullptr);

    // MoE branch (top-2 gathered rows per expert; tiles beyond count[e] exit)
    dim3 gMgu(MM / BN, TT / BM, NE);
    sgemm_kernel<<<gMgu, 256>>>(p_moe_in, HH, 0, we_gate, MM, (long long)HH * MM,
                                p_bufG, MM, (long long)TT * MM, HH, p_tok, TT, p_cur);
    sgemm_kernel<<<gMgu, 256>>>(p_moe_in, HH, 0, we_up,   MM, (long long)HH * MM,
                                p_bufU, MM, (long long)TT * MM, HH, p_tok, TT, p_cur);
    glumul_moe_kernel<<<ECAP, 256>>>();
    dim3 gMd(HH / BN, TT / BM, NE);
    sgemm_kernel<<<gMd, 256>>>(p_bufH, MM, (long long)TT * MM, we_down, HH, (long long)MM * HH,
                               p_eo, HH, (long long)TT * HH, MM, nullptr, 0, p_cur);

    final_kernel<<<TT, 256>>>(rn_post1, rn_post2, rn_post, out);
}